// round 14
// baseline (speedup 1.0000x reference)
#include <cuda_runtime.h>
#include <cstdint>

#define NN 50000
#define EE 800000
#define CIN 32
#define CH 64
#define COUT 16
#define TE 256   // edges per tile in edgeconv
#define NT ((EE + TE - 1) / TE)
#define SB 1024  // scan block size
#define SNB ((NN + SB - 1) / SB)   // 49

// edgeconv smem layout (float offsets)
// region0: u [64][260] = 16640 floats  /  msh [256][68] = 17408 floats (aliased)
#define EC_R0   17408
#define EC_W2   EC_R0
#define EC_B2   (EC_W2 + 4096)
#define EC_COL  (EC_B2 + 64)
#define EC_SRC  (EC_COL + 256)
#define EC_FLTS (EC_SRC + 256)   // 21824 floats = 87296 B

// ---------------- scratch (device globals; zero-initialized at load) ----------------
__device__ float d_dinv[NN];
__device__ int   d_cnt[NN];        // re-zeroed by k_scan3 each call
__device__ int   d_rowptr[NN + 1];
__device__ int   d_fill[NN];
__device__ int   d_bsum[64];
__device__ int2  d_edge[EE];       // CSR: {src,col}, grouped by col
__device__ float d_h1[NN * CH];
__device__ float d_P[NN * CH];
__device__ float d_Q[NN * CH];
__device__ float d_h2[NN * CH];    // re-zeroed by k_z each call
__device__ float d_z[NN * COUT];

// ---------------- f32x2 packed helpers (FFMA2: 2x fp32 FMA/inst, bit-exact) ----
__device__ __forceinline__ void fma2(unsigned long long& d, unsigned long long a,
                                     unsigned long long b) {
    asm("fma.rn.f32x2 %0, %1, %2, %0;" : "+l"(d) : "l"(a), "l"(b));
}
__device__ __forceinline__ unsigned long long pack2(float lo, float hi) {
    unsigned long long r;
    asm("mov.b64 %0, {%1, %2};" : "=l"(r) : "f"(lo), "f"(hi));
    return r;
}
__device__ __forceinline__ unsigned long long add2(unsigned long long a,
                                                   unsigned long long b) {
    unsigned long long r;
    asm("add.rn.f32x2 %0, %1, %2;" : "=l"(r) : "l"(a), "l"(b));
    return r;
}

// ---------------- kernels ----------------

// histogram over col (edge_index is int32 on device)
__global__ void k_prep(const int* __restrict__ ei) {
    int e = blockIdx.x * blockDim.x + threadIdx.x;
    if (e >= EE) return;
    int c = ei[EE + e];
    if ((unsigned)c >= NN) c = 0;
    atomicAdd(&d_cnt[c], 1);
}

__global__ void k_scan1() {
    __shared__ int sh[SB];
    int idx = blockIdx.x * SB + threadIdx.x;
    sh[threadIdx.x] = (idx < NN) ? d_cnt[idx] : 0;
    __syncthreads();
    for (int off = SB / 2; off > 0; off >>= 1) {
        if (threadIdx.x < off) sh[threadIdx.x] += sh[threadIdx.x + off];
        __syncthreads();
    }
    if (threadIdx.x == 0) d_bsum[blockIdx.x] = sh[0];
}

// scan of block sums folded in: each block re-scans the 49 sums locally
__global__ void k_scan3() {
    __shared__ int sh[SB];
    __shared__ int shb[64];
    int t = threadIdx.x;
    if (t < 64) shb[t] = (t < SNB) ? d_bsum[t] : 0;
    int idx = blockIdx.x * SB + t;
    int v = (idx < NN) ? d_cnt[idx] : 0;
    sh[t] = v;
    __syncthreads();
    for (int off = 1; off < SB; off <<= 1) {
        int u = (t >= off) ? sh[t - off] : 0;
        __syncthreads();
        sh[t] += u;
        if (off < 64 && t < 64) {
            int ub = (t >= off) ? shb[t - off] : 0;
            __syncthreads();
            shb[t] += ub;
        } else {
            __syncthreads();
        }
        __syncthreads();
    }
    int boff = (blockIdx.x > 0) ? shb[blockIdx.x - 1] : 0;  // exclusive prefix
    if (idx < NN) {
        int pos = boff + sh[t] - v;
        d_rowptr[idx] = pos;
        d_fill[idx]   = pos;
        d_dinv[idx]   = rsqrtf((float)v + 1.0f);
        d_cnt[idx]    = 0;   // reset for next call (graph replays)
    }
    if (idx == 0) d_rowptr[NN] = EE;
}

__global__ void k_scatter(const int* __restrict__ ei) {
    int e = blockIdx.x * blockDim.x + threadIdx.x;
    if (e >= EE) return;
    int r = ei[e];
    int c = ei[EE + e];
    if ((unsigned)r >= NN) r = 0;
    if ((unsigned)c >= NN) c = 0;
    int pos = atomicAdd(&d_fill[c], 1);
    d_edge[pos] = make_int2(r, c);
}

// Fused GCN1: gather (warp per node) + matmul + tanh. Persistent.
__global__ void __launch_bounds__(256) k_h1(const float* __restrict__ x,
                                            const float* __restrict__ w,
                                            const float* __restrict__ bb) {
    __shared__ float ws[CIN * CH];
    __shared__ float bs[CH];
    __shared__ float ys[8][CIN];
    int tid = threadIdx.x;
    for (int i = tid; i < CIN * CH; i += 256) ws[i] = w[i];
    if (tid < CH) bs[tid] = bb[tid];
    __syncthreads();
    int warp = tid >> 5, lane = tid & 31;
    for (int c = blockIdx.x * 8 + warp; c < NN; c += gridDim.x * 8) {
        int beg = d_rowptr[c], end = d_rowptr[c + 1];
        float s0 = 0.f, s1 = 0.f, s2 = 0.f, s3 = 0.f;
        int i = beg;
        for (; i + 3 < end; i += 4) {
            int2 e0 = __ldg(&d_edge[i]);
            int2 e1 = __ldg(&d_edge[i + 1]);
            int2 e2 = __ldg(&d_edge[i + 2]);
            int2 e3 = __ldg(&d_edge[i + 3]);
            s0 += __ldg(&d_dinv[e0.x]) * __ldg(&x[e0.x * CIN + lane]);
            s1 += __ldg(&d_dinv[e1.x]) * __ldg(&x[e1.x * CIN + lane]);
            s2 += __ldg(&d_dinv[e2.x]) * __ldg(&x[e2.x * CIN + lane]);
            s3 += __ldg(&d_dinv[e3.x]) * __ldg(&x[e3.x * CIN + lane]);
        }
        for (; i < end; i++) {
            int2 e0 = __ldg(&d_edge[i]);
            s0 += __ldg(&d_dinv[e0.x]) * __ldg(&x[e0.x * CIN + lane]);
        }
        float dc = d_dinv[c];
        ys[warp][lane] = dc * ((s0 + s1) + (s2 + s3) + dc * x[c * CIN + lane]);
        __syncwarp();
        float a0 = bs[lane], a1 = bs[lane + 32];
#pragma unroll
        for (int j = 0; j < CIN; j++) {
            float yv = ys[warp][j];
            a0 += yv * ws[j * CH + lane];
            a1 += yv * ws[j * CH + lane + 32];
        }
        d_h1[c * CH + lane]      = tanhf(a0);
        d_h1[c * CH + lane + 32] = tanhf(a1);
        __syncwarp();
    }
}

// [P|Q] = h1 @ [W1a-W1b | W1b]: register-tiled GEMM with f32x2.
__global__ void __launch_bounds__(256) k_pq(const float* __restrict__ w1,
                                            const float* __restrict__ b1) {
    extern __shared__ float pqsm[];
    float* wsm = pqsm;              // [64][128]
    float* bsm = wsm + 64 * 128;
    float* ht  = bsm + 64;          // [64][68]
    int tid = threadIdx.x;

    for (int i = tid; i < 64 * 64; i += 256) {
        int j = i >> 6, k = i & 63;
        float hi = w1[(64 + j) * 64 + k];
        wsm[j * 128 + k]      = w1[j * 64 + k] - hi;
        wsm[j * 128 + 64 + k] = hi;
    }
    if (tid < 64) bsm[tid] = b1[tid];
    int nb0 = blockIdx.x * 64;
    for (int i = tid; i < 64 * 64; i += 256) {
        int node = i >> 6, j = i & 63;
        int g = nb0 + node;
        ht[j * 68 + node] = (g < NN) ? d_h1[g * 64 + j] : 0.f;
    }
    __syncthreads();

    int cg = tid & 15;
    int rg = tid >> 4;
    unsigned long long acc[4][4];
#pragma unroll
    for (int i = 0; i < 4; i++)
#pragma unroll
        for (int n = 0; n < 4; n++) acc[i][n] = 0ULL;

#pragma unroll 4
    for (int jj = 0; jj < 64; jj++) {
        float4 a = *(const float4*)&ht[jj * 68 + rg * 4];
        const unsigned long long* bp =
            (const unsigned long long*)&wsm[jj * 128 + cg * 8];
        unsigned long long b0 = bp[0], b1v = bp[1], b2 = bp[2], b3 = bp[3];
        float av[4] = {a.x, a.y, a.z, a.w};
#pragma unroll
        for (int i = 0; i < 4; i++) {
            unsigned long long ap = pack2(av[i], av[i]);
            fma2(acc[i][0], ap, b0);
            fma2(acc[i][1], ap, b1v);
            fma2(acc[i][2], ap, b2);
            fma2(acc[i][3], ap, b3);
        }
    }

    if (cg < 8) {
        unsigned long long bb[4];
#pragma unroll
        for (int n = 0; n < 4; n++) bb[n] = pack2(bsm[cg * 8 + 2 * n], bsm[cg * 8 + 2 * n + 1]);
#pragma unroll
        for (int i = 0; i < 4; i++) {
            int g = nb0 + rg * 4 + i;
            if (g >= NN) continue;
            unsigned long long* dst = (unsigned long long*)&d_P[g * 64 + cg * 8];
#pragma unroll
            for (int n = 0; n < 4; n++) dst[n] = add2(acc[i][n], bb[n]);
        }
    } else {
#pragma unroll
        for (int i = 0; i < 4; i++) {
            int g = nb0 + rg * 4 + i;
            if (g >= NN) continue;
            unsigned long long* dst = (unsigned long long*)&d_Q[g * 64 + (cg - 8) * 8];
#pragma unroll
            for (int n = 0; n < 4; n++) dst[n] = acc[i][n];
        }
    }
}

// EdgeConv, persistent, TE=256, 512 threads.
// Phase B: warp -> (k-slice kg = wid&7 [broadcast b], edge-half eh = wid>>3).
__global__ void __launch_bounds__(512) k_edgeconv(const float* __restrict__ w2,
                                                  const float* __restrict__ b2) {
    extern __shared__ float sm[];
    float* u    = sm;                 // [64][260] transposed u
    float* msh  = sm;                 // [256][68], aliases u
    float* w2s  = sm + EC_W2;         // [64][64]
    float* b2s  = sm + EC_B2;         // [64]
    int*   cols = (int*)(sm + EC_COL);
    int*   srcs = (int*)(sm + EC_SRC);

    int tid = threadIdx.x, wid = tid >> 5, lane = tid & 31;
    for (int i = tid; i < 64 * 64; i += 512) w2s[i] = w2[i];
    if (tid < 64) b2s[tid] = b2[tid];

    int ea = tid >> 1;           // Phase A: edge (0..255)
    int jh = (tid & 1) * 8;      // Phase A: float4-chunk base
    int kg = wid & 7;            // Phase B: k-slice
    int eh = (wid >> 3) * 128;   // Phase B: edge-half base

    for (int tile = blockIdx.x; tile < NT; tile += gridDim.x) {
        __syncthreads();  // prev iter's Phase C reads of cols/msh complete
        if (tid < TE) {
            int idx = tile * TE + tid;
            if (idx < EE) { int2 e = __ldg(&d_edge[idx]); srcs[tid] = e.x; cols[tid] = e.y; }
            else          { cols[tid] = -1;               srcs[tid] = 0; }
        }
        __syncthreads();

        // Phase A: u[j][e] = relu(P[c][j] + Q[r][j]); float4 loads
        {
            int c = cols[ea], r = srcs[ea];
            if (c >= 0) {
                const float4* Pp = (const float4*)&d_P[c * 64];
                const float4* Qp = (const float4*)&d_Q[r * 64];
#pragma unroll
                for (int cc = 0; cc < 8; cc++) {
                    float4 p = __ldg(&Pp[jh + cc]);
                    float4 q = __ldg(&Qp[jh + cc]);
                    int j = (jh + cc) * 4;
                    u[(j + 0) * 260 + ea] = fmaxf(p.x + q.x, 0.f);
                    u[(j + 1) * 260 + ea] = fmaxf(p.y + q.y, 0.f);
                    u[(j + 2) * 260 + ea] = fmaxf(p.z + q.z, 0.f);
                    u[(j + 3) * 260 + ea] = fmaxf(p.w + q.w, 0.f);
                }
            } else {
#pragma unroll
                for (int cc = 0; cc < 8; cc++) {
                    int j = (jh + cc) * 4;
                    u[(j + 0) * 260 + ea] = 0.f;
                    u[(j + 1) * 260 + ea] = 0.f;
                    u[(j + 2) * 260 + ea] = 0.f;
                    u[(j + 3) * 260 + ea] = 0.f;
                }
            }
        }
        __syncthreads();

        // Phase B: warp owns k-slice kg*8..+8 over edges eh..eh+127; lane: 4 edges.
        unsigned long long acc[4][4];
#pragma unroll
        for (int i = 0; i < 4; i++)
#pragma unroll
            for (int n = 0; n < 4; n++) acc[i][n] = 0ULL;

#pragma unroll 4
        for (int jj = 0; jj < 64; jj++) {
            float4 a = *(const float4*)&u[jj * 260 + eh + lane * 4];
            const unsigned long long* bp =
                (const unsigned long long*)&w2s[jj * 64 + kg * 8];
            unsigned long long b0 = bp[0], b1v = bp[1], b2v = bp[2], b3 = bp[3];
            float av[4] = {a.x, a.y, a.z, a.w};
#pragma unroll
            for (int i = 0; i < 4; i++) {
                unsigned long long ap = pack2(av[i], av[i]);
                fma2(acc[i][0], ap, b0);
                fma2(acc[i][1], ap, b1v);
                fma2(acc[i][2], ap, b2v);
                fma2(acc[i][3], ap, b3);
            }
        }
        __syncthreads();  // all reads of u done before overwrite with msh

#pragma unroll
        for (int i = 0; i < 4; i++) {
            int e = eh + lane * 4 + i;
            unsigned long long* mp = (unsigned long long*)&msh[e * 68 + kg * 8];
#pragma unroll
            for (int n = 0; n < 4; n++) mp[n] = acc[i][n];
        }
        __syncthreads();

        // Phase C: per-(col-run, k) max; flush via atomicMax (positive-float-as-int)
        {
            int k = tid & 63;
            int part = tid >> 6;   // 0..7, 32 edges each
            float mx = -3.0e38f;
            int cur = -1;
            for (int e = part * 32; e < part * 32 + 32; e++) {
                int c = cols[e];
                if (c != cur) {
                    if (cur >= 0) {
                        float v = mx + b2s[k];
                        if (v > 0.f) atomicMax((int*)&d_h2[cur * 64 + k], __float_as_int(v));
                    }
                    cur = c;
                    mx = -3.0e38f;
                }
                mx = fmaxf(mx, msh[e * 68 + k]);
            }
            if (cur >= 0) {
                float v = mx + b2s[k];
                if (v > 0.f) atomicMax((int*)&d_h2[cur * 64 + k], __float_as_int(v));
            }
        }
    }
}

// z = h2 @ gcn2_w; then zero this block's h2 chunk for next call
__global__ void k_z(const float* __restrict__ w) {
    __shared__ float ws[CH * COUT];
    for (int i = threadIdx.x; i < CH * COUT; i += blockDim.x) ws[i] = w[i];
    __syncthreads();
    int t = blockIdx.x * blockDim.x + threadIdx.x;   // grid exactly NN*COUT
    int c = t >> 4, k = t & 15;
    const float* hr = &d_h2[c * CH];
    float acc = 0.f;
#pragma unroll 8
    for (int j = 0; j < CH; j++) acc += hr[j] * ws[j * COUT + k];
    d_z[t] = acc;
    __syncthreads();
    float4* hz = (float4*)&d_h2[(size_t)blockIdx.x * 1024];
    hz[threadIdx.x] = make_float4(0.f, 0.f, 0.f, 0.f);
}

// out[c] = dinv[c]*(sum_r dinv[r]*z[r] + dinv[c]*z[c]) + b ; 2 nodes per warp
__global__ void k_out(const float* __restrict__ b, float* __restrict__ out) {
    int gw = (blockIdx.x * blockDim.x + threadIdx.x) >> 5;
    int lane = threadIdx.x & 31;
    int c = gw * 2 + (lane >> 4);
    int l = lane & 15;
    if (c >= NN) return;
    int beg = d_rowptr[c], end = d_rowptr[c + 1];
    float s0 = 0.f, s1 = 0.f, s2 = 0.f, s3 = 0.f;
    int i = beg;
    for (; i + 3 < end; i += 4) {
        int2 e0 = __ldg(&d_edge[i]);
        int2 e1 = __ldg(&d_edge[i + 1]);
        int2 e2 = __ldg(&d_edge[i + 2]);
        int2 e3 = __ldg(&d_edge[i + 3]);
        s0 += __ldg(&d_dinv[e0.x]) * __ldg(&d_z[e0.x * COUT + l]);
        s1 += __ldg(&d_dinv[e1.x]) * __ldg(&d_z[e1.x * COUT + l]);
        s2 += __ldg(&d_dinv[e2.x]) * __ldg(&d_z[e2.x * COUT + l]);
        s3 += __ldg(&d_dinv[e3.x]) * __ldg(&d_z[e3.x * COUT + l]);
    }
    for (; i < end; i++) {
        int2 e0 = __ldg(&d_edge[i]);
        s0 += __ldg(&d_dinv[e0.x]) * __ldg(&d_z[e0.x * COUT + l]);
    }
    float dc = d_dinv[c];
    out[c * COUT + l] = dc * ((s0 + s1) + (s2 + s3) + dc * d_z[c * COUT + l]) + b[l];
}

// ---------------- launch ----------------
extern "C" void kernel_launch(void* const* d_in, const int* in_sizes, int n_in,
                              void* d_out, int out_size) {
    const float* x   = (const float*)d_in[0];
    const int*   ei  = (const int*)d_in[1];
    const float* g1w = (const float*)d_in[2];
    const float* g1b = (const float*)d_in[3];
    const float* e1w = (const float*)d_in[4];
    const float* e1b = (const float*)d_in[5];
    const float* e2w = (const float*)d_in[6];
    const float* e2b = (const float*)d_in[7];
    const float* g2w = (const float*)d_in[8];
    const float* g2b = (const float*)d_in[9];
    float* out = (float*)d_out;

    k_prep<<<(EE + 255) / 256, 256>>>(ei);
    k_scan1<<<SNB, SB>>>();
    k_scan3<<<SNB, SB>>>();
    k_scatter<<<(EE + 255) / 256, 256>>>(ei);
    k_h1<<<1184, 256>>>(x, g1w, g1b);

    int pqsmem = (64 * 128 + 64 + 64 * 68) * (int)sizeof(float);
    cudaFuncSetAttribute(k_pq, cudaFuncAttributeMaxDynamicSharedMemorySize, pqsmem);
    k_pq<<<(NN + 63) / 64, 256, pqsmem>>>(e1w, e1b);

    int smem = EC_FLTS * (int)sizeof(float);
    cudaFuncSetAttribute(k_edgeconv, cudaFuncAttributeMaxDynamicSharedMemorySize, smem);
    k_edgeconv<<<296, 512, smem>>>(e2w, e2b);

    k_z<<<(NN * COUT + 255) / 256, 256>>>(g2w);
    k_out<<<(NN * 16 + 255) / 256, 256>>>(g2b, out);
}

// round 15
// speedup vs baseline: 1.0121x; 1.0121x over previous
#include <cuda_runtime.h>
#include <cstdint>

#define NN 50000
#define EE 800000
#define CIN 32
#define CH 64
#define COUT 16
#define TE 128   // edges per tile in edgeconv
#define NT ((EE + TE - 1) / TE)
#define SB 1024  // scan block size
#define SNB ((NN + SB - 1) / SB)   // 49

// edgeconv smem layout (float offsets) — R12-proven TE=128 shape
#define EC_R0   8704          // region0: u [64][132]=8448 / msh [128][68]=8704 (aliased)
#define EC_W2   EC_R0         // w2s [64][64]
#define EC_B2   (EC_W2 + 4096)
#define EC_COL  (EC_B2 + 64)
#define EC_SRC  (EC_COL + 128)
#define EC_FLTS (EC_SRC + 128)   // 13120 floats = 52480 B

// ---------------- scratch (device globals; zero-initialized at load) ----------------
__device__ float d_dinv[NN];
__device__ int   d_cnt[NN];        // re-zeroed by k_scan3 each call
__device__ int   d_rowptr[NN + 1];
__device__ int   d_fill[NN];
__device__ int   d_bsum[64];
__device__ int2  d_edge[EE];       // CSR: {src,col}, grouped by col
__device__ float d_P[NN * CH];
__device__ float d_Q[NN * CH];
__device__ float d_h2[NN * CH];    // re-zeroed by k_z each call
__device__ float d_z[NN * COUT];

// ---------------- f32x2 packed helpers (FFMA2: 2x fp32 FMA/inst, bit-exact) ----
__device__ __forceinline__ void fma2(unsigned long long& d, unsigned long long a,
                                     unsigned long long b) {
    asm("fma.rn.f32x2 %0, %1, %2, %0;" : "+l"(d) : "l"(a), "l"(b));
}
__device__ __forceinline__ unsigned long long pack2(float lo, float hi) {
    unsigned long long r;
    asm("mov.b64 %0, {%1, %2};" : "=l"(r) : "f"(lo), "f"(hi));
    return r;
}
__device__ __forceinline__ unsigned long long add2(unsigned long long a,
                                                   unsigned long long b) {
    unsigned long long r;
    asm("add.rn.f32x2 %0, %1, %2;" : "=l"(r) : "l"(a), "l"(b));
    return r;
}

// ---------------- kernels ----------------

// histogram over col (edge_index is int32 on device)
__global__ void k_prep(const int* __restrict__ ei) {
    int e = blockIdx.x * blockDim.x + threadIdx.x;
    if (e >= EE) return;
    int c = ei[EE + e];
    if ((unsigned)c >= NN) c = 0;
    atomicAdd(&d_cnt[c], 1);
}

__global__ void k_scan1() {
    __shared__ int sh[SB];
    int idx = blockIdx.x * SB + threadIdx.x;
    sh[threadIdx.x] = (idx < NN) ? d_cnt[idx] : 0;
    __syncthreads();
    for (int off = SB / 2; off > 0; off >>= 1) {
        if (threadIdx.x < off) sh[threadIdx.x] += sh[threadIdx.x + off];
        __syncthreads();
    }
    if (threadIdx.x == 0) d_bsum[blockIdx.x] = sh[0];
}

// scan with block-sum scan folded in (each block re-scans the 49 sums locally)
__global__ void k_scan3() {
    __shared__ int sh[SB];
    __shared__ int shb[64];
    int t = threadIdx.x;
    if (t < 64) shb[t] = (t < SNB) ? d_bsum[t] : 0;
    int idx = blockIdx.x * SB + t;
    int v = (idx < NN) ? d_cnt[idx] : 0;
    sh[t] = v;
    __syncthreads();
    for (int off = 1; off < SB; off <<= 1) {
        int u = (t >= off) ? sh[t - off] : 0;
        __syncthreads();
        sh[t] += u;
        if (off < 64 && t < 64) {
            int ub = (t >= off) ? shb[t - off] : 0;
            __syncthreads();
            shb[t] += ub;
        } else {
            __syncthreads();
        }
        __syncthreads();
    }
    int boff = (blockIdx.x > 0) ? shb[blockIdx.x - 1] : 0;
    if (idx < NN) {
        int pos = boff + sh[t] - v;
        d_rowptr[idx] = pos;
        d_fill[idx]   = pos;
        d_dinv[idx]   = rsqrtf((float)v + 1.0f);
        d_cnt[idx]    = 0;   // reset for next graph replay
    }
    if (idx == 0) d_rowptr[NN] = EE;
}

__global__ void k_scatter(const int* __restrict__ ei) {
    int e = blockIdx.x * blockDim.x + threadIdx.x;
    if (e >= EE) return;
    int r = ei[e];
    int c = ei[EE + e];
    if ((unsigned)r >= NN) r = 0;
    if ((unsigned)c >= NN) c = 0;
    int pos = atomicAdd(&d_fill[c], 1);
    d_edge[pos] = make_int2(r, c);
}

// Fused GCN1 + PQ: block owns 64 nodes. Gather x -> y -> h1=tanh(...) written
// transposed into smem ht; then [P|Q] = ht^T @ [W1a-W1b | W1b] register-tiled GEMM.
// No d_h1 global round trip.
__global__ void __launch_bounds__(256) k_hpq(const float* __restrict__ x,
                                             const float* __restrict__ g1w,
                                             const float* __restrict__ g1b,
                                             const float* __restrict__ e1w,
                                             const float* __restrict__ e1b) {
    extern __shared__ float sm[];
    float* ws1 = sm;               // [32][64] gcn1 weights
    float* bs1 = ws1 + CIN * CH;   // [64]
    float* wsm = bs1 + 64;         // [64][128]: cols 0-63 = W1a-W1b, 64-127 = W1b
    float* bsm = wsm + 64 * 128;   // [64]
    float* ht  = bsm + 64;         // [64][68] transposed h1 tile
    float* ys  = ht + 64 * 68;     // [8][32]
    int tid = threadIdx.x;
    int warp = tid >> 5, lane = tid & 31;

    for (int i = tid; i < CIN * CH; i += 256) ws1[i] = g1w[i];
    for (int i = tid; i < 64 * 64; i += 256) {
        int j = i >> 6, k = i & 63;
        float hi = e1w[(64 + j) * 64 + k];
        wsm[j * 128 + k]      = e1w[j * 64 + k] - hi;
        wsm[j * 128 + 64 + k] = hi;
    }
    if (tid < 64) { bs1[tid] = g1b[tid]; bsm[tid] = e1b[tid]; }
    __syncthreads();

    int nb0 = blockIdx.x * 64;

    // Phase G: 8 warps x 8 rounds = 64 nodes; h1 -> ht (transposed)
    for (int r8 = 0; r8 < 8; r8++) {
        int node = r8 * 8 + warp;
        int c = nb0 + node;
        if (c < NN) {
            int beg = d_rowptr[c], end = d_rowptr[c + 1];
            float s0 = 0.f, s1 = 0.f, s2 = 0.f, s3 = 0.f;
            int i = beg;
            for (; i + 3 < end; i += 4) {
                int2 e0 = __ldg(&d_edge[i]);
                int2 e1 = __ldg(&d_edge[i + 1]);
                int2 e2 = __ldg(&d_edge[i + 2]);
                int2 e3 = __ldg(&d_edge[i + 3]);
                s0 += __ldg(&d_dinv[e0.x]) * __ldg(&x[e0.x * CIN + lane]);
                s1 += __ldg(&d_dinv[e1.x]) * __ldg(&x[e1.x * CIN + lane]);
                s2 += __ldg(&d_dinv[e2.x]) * __ldg(&x[e2.x * CIN + lane]);
                s3 += __ldg(&d_dinv[e3.x]) * __ldg(&x[e3.x * CIN + lane]);
            }
            for (; i < end; i++) {
                int2 e0 = __ldg(&d_edge[i]);
                s0 += __ldg(&d_dinv[e0.x]) * __ldg(&x[e0.x * CIN + lane]);
            }
            float dc = d_dinv[c];
            ys[warp * 32 + lane] = dc * ((s0 + s1) + (s2 + s3) + dc * x[c * CIN + lane]);
            __syncwarp();
            float a0 = bs1[lane], a1 = bs1[lane + 32];
#pragma unroll
            for (int j = 0; j < CIN; j++) {
                float yv = ys[warp * 32 + j];
                a0 += yv * ws1[j * CH + lane];
                a1 += yv * ws1[j * CH + lane + 32];
            }
            ht[lane * 68 + node]        = tanhf(a0);
            ht[(lane + 32) * 68 + node] = tanhf(a1);
            __syncwarp();
        } else {
            ht[lane * 68 + node]        = 0.f;
            ht[(lane + 32) * 68 + node] = 0.f;
        }
    }
    __syncthreads();

    // Phase PQ: register-tiled GEMM with f32x2 (as proven k_pq)
    int cg = tid & 15;
    int rg = tid >> 4;
    unsigned long long acc[4][4];
#pragma unroll
    for (int i = 0; i < 4; i++)
#pragma unroll
        for (int n = 0; n < 4; n++) acc[i][n] = 0ULL;

#pragma unroll 4
    for (int jj = 0; jj < 64; jj++) {
        float4 a = *(const float4*)&ht[jj * 68 + rg * 4];
        const unsigned long long* bp =
            (const unsigned long long*)&wsm[jj * 128 + cg * 8];
        unsigned long long b0 = bp[0], b1v = bp[1], b2 = bp[2], b3 = bp[3];
        float av[4] = {a.x, a.y, a.z, a.w};
#pragma unroll
        for (int i = 0; i < 4; i++) {
            unsigned long long ap = pack2(av[i], av[i]);
            fma2(acc[i][0], ap, b0);
            fma2(acc[i][1], ap, b1v);
            fma2(acc[i][2], ap, b2);
            fma2(acc[i][3], ap, b3);
        }
    }

    if (cg < 8) {
        unsigned long long bb[4];
#pragma unroll
        for (int n = 0; n < 4; n++) bb[n] = pack2(bsm[cg * 8 + 2 * n], bsm[cg * 8 + 2 * n + 1]);
#pragma unroll
        for (int i = 0; i < 4; i++) {
            int g = nb0 + rg * 4 + i;
            if (g >= NN) continue;
            unsigned long long* dst = (unsigned long long*)&d_P[g * 64 + cg * 8];
#pragma unroll
            for (int n = 0; n < 4; n++) dst[n] = add2(acc[i][n], bb[n]);
        }
    } else {
#pragma unroll
        for (int i = 0; i < 4; i++) {
            int g = nb0 + rg * 4 + i;
            if (g >= NN) continue;
            unsigned long long* dst = (unsigned long long*)&d_Q[g * 64 + (cg - 8) * 8];
#pragma unroll
            for (int n = 0; n < 4; n++) dst[n] = acc[i][n];
        }
    }
}

// EdgeConv, persistent, TE=128 (R12-proven). Phase B: warp = 8-wide k-slice
// (b loads warp-broadcast), lanes = 4 edges each.
__global__ void __launch_bounds__(256) k_edgeconv(const float* __restrict__ w2,
                                                  const float* __restrict__ b2) {
    extern __shared__ float sm[];
    float* u    = sm;                 // [64][132] transposed u
    float* msh  = sm;                 // [128][68], aliases u
    float* w2s  = sm + EC_W2;         // [64][64]
    float* b2s  = sm + EC_B2;         // [64]
    int*   cols = (int*)(sm + EC_COL);
    int*   srcs = (int*)(sm + EC_SRC);

    int tid = threadIdx.x, wid = tid >> 5, lane = tid & 31;
    for (int i = tid; i < 64 * 64; i += 256) w2s[i] = w2[i];
    if (tid < 64) b2s[tid] = b2[tid];

    int ea = tid >> 1;           // Phase A: edge
    int jh = (tid & 1) * 8;      // Phase A: float4-chunk base

    for (int tile = blockIdx.x; tile < NT; tile += gridDim.x) {
        __syncthreads();  // prev iter's Phase C reads of cols/msh complete
        if (tid < TE) {
            int idx = tile * TE + tid;
            if (idx < EE) { int2 e = __ldg(&d_edge[idx]); srcs[tid] = e.x; cols[tid] = e.y; }
            else          { cols[tid] = -1;               srcs[tid] = 0; }
        }
        __syncthreads();

        // Phase A: u[j][e] = relu(P[c][j] + Q[r][j]); float4 loads
        {
            int c = cols[ea], r = srcs[ea];
            if (c >= 0) {
                const float4* Pp = (const float4*)&d_P[c * 64];
                const float4* Qp = (const float4*)&d_Q[r * 64];
#pragma unroll
                for (int cc = 0; cc < 8; cc++) {
                    float4 p = __ldg(&Pp[jh + cc]);
                    float4 q = __ldg(&Qp[jh + cc]);
                    int j = (jh + cc) * 4;
                    u[(j + 0) * 132 + ea] = fmaxf(p.x + q.x, 0.f);
                    u[(j + 1) * 132 + ea] = fmaxf(p.y + q.y, 0.f);
                    u[(j + 2) * 132 + ea] = fmaxf(p.z + q.z, 0.f);
                    u[(j + 3) * 132 + ea] = fmaxf(p.w + q.w, 0.f);
                }
            } else {
#pragma unroll
                for (int cc = 0; cc < 8; cc++) {
                    int j = (jh + cc) * 4;
                    u[(j + 0) * 132 + ea] = 0.f;
                    u[(j + 1) * 132 + ea] = 0.f;
                    u[(j + 2) * 132 + ea] = 0.f;
                    u[(j + 3) * 132 + ea] = 0.f;
                }
            }
        }
        __syncthreads();

        // Phase B: warp wid owns k-slice wid*8..+8; lane owns edges lane*4..+3.
        unsigned long long acc[4][4];
#pragma unroll
        for (int i = 0; i < 4; i++)
#pragma unroll
            for (int n = 0; n < 4; n++) acc[i][n] = 0ULL;

#pragma unroll 4
        for (int jj = 0; jj < 64; jj++) {
            float4 a = *(const float4*)&u[jj * 132 + lane * 4];
            const unsigned long long* bp =
                (const unsigned long long*)&w2s[jj * 64 + wid * 8];
            unsigned long long b0 = bp[0], b1v = bp[1], b2v = bp[2], b3 = bp[3];
            float av[4] = {a.x, a.y, a.z, a.w};
#pragma unroll
            for (int i = 0; i < 4; i++) {
                unsigned long long ap = pack2(av[i], av[i]);
                fma2(acc[i][0], ap, b0);
                fma2(acc[i][1], ap, b1v);
                fma2(acc[i][2], ap, b2v);
                fma2(acc[i][3], ap, b3);
            }
        }
        __syncthreads();  // all reads of u done before overwrite with msh

#pragma unroll
        for (int i = 0; i < 4; i++) {
            int e = lane * 4 + i;
            unsigned long long* mp = (unsigned long long*)&msh[e * 68 + wid * 8];
#pragma unroll
            for (int n = 0; n < 4; n++) mp[n] = acc[i][n];
        }
        __syncthreads();

        // Phase C: per-(col-run, k) max; flush via atomicMax (positive-float-as-int)
        {
            int k = tid & 63;
            int part = tid >> 6;
            float mx = -3.0e38f;
            int cur = -1;
            for (int e = part * 32; e < part * 32 + 32; e++) {
                int c = cols[e];
                if (c != cur) {
                    if (cur >= 0) {
                        float v = mx + b2s[k];
                        if (v > 0.f) atomicMax((int*)&d_h2[cur * 64 + k], __float_as_int(v));
                    }
                    cur = c;
                    mx = -3.0e38f;
                }
                mx = fmaxf(mx, msh[e * 68 + k]);
            }
            if (cur >= 0) {
                float v = mx + b2s[k];
                if (v > 0.f) atomicMax((int*)&d_h2[cur * 64 + k], __float_as_int(v));
            }
        }
    }
}

// z = h2 @ gcn2_w; then zero this block's h2 chunk for next call
__global__ void k_z(const float* __restrict__ w) {
    __shared__ float ws[CH * COUT];
    for (int i = threadIdx.x; i < CH * COUT; i += blockDim.x) ws[i] = w[i];
    __syncthreads();
    int t = blockIdx.x * blockDim.x + threadIdx.x;   // grid exactly NN*COUT
    int c = t >> 4, k = t & 15;
    const float* hr = &d_h2[c * CH];
    float acc = 0.f;
#pragma unroll 8
    for (int j = 0; j < CH; j++) acc += hr[j] * ws[j * COUT + k];
    d_z[t] = acc;
    __syncthreads();
    float4* hz = (float4*)&d_h2[(size_t)blockIdx.x * 1024];
    hz[threadIdx.x] = make_float4(0.f, 0.f, 0.f, 0.f);
}

// out[c] = dinv[c]*(sum_r dinv[r]*z[r] + dinv[c]*z[c]) + b ; 2 nodes per warp
__global__ void k_out(const float* __restrict__ b, float* __restrict__ out) {
    int gw = (blockIdx.x * blockDim.x + threadIdx.x) >> 5;
    int lane = threadIdx.x & 31;
    int c = gw * 2 + (lane >> 4);
    int l = lane & 15;
    if (c >= NN) return;
    int beg = d_rowptr[c], end = d_rowptr[c + 1];
    float s0 = 0.f, s1 = 0.f, s2 = 0.f, s3 = 0.f;
    int i = beg;
    for (; i + 3 < end; i += 4) {
        int2 e0 = __ldg(&d_edge[i]);
        int2 e1 = __ldg(&d_edge[i + 1]);
        int2 e2 = __ldg(&d_edge[i + 2]);
        int2 e3 = __ldg(&d_edge[i + 3]);
        s0 += __ldg(&d_dinv[e0.x]) * __ldg(&d_z[e0.x * COUT + l]);
        s1 += __ldg(&d_dinv[e1.x]) * __ldg(&d_z[e1.x * COUT + l]);
        s2 += __ldg(&d_dinv[e2.x]) * __ldg(&d_z[e2.x * COUT + l]);
        s3 += __ldg(&d_dinv[e3.x]) * __ldg(&d_z[e3.x * COUT + l]);
    }
    for (; i < end; i++) {
        int2 e0 = __ldg(&d_edge[i]);
        s0 += __ldg(&d_dinv[e0.x]) * __ldg(&d_z[e0.x * COUT + l]);
    }
    float dc = d_dinv[c];
    out[c * COUT + l] = dc * ((s0 + s1) + (s2 + s3) + dc * d_z[c * COUT + l]) + b[l];
}

// ---------------- launch ----------------
extern "C" void kernel_launch(void* const* d_in, const int* in_sizes, int n_in,
                              void* d_out, int out_size) {
    const float* x   = (const float*)d_in[0];
    const int*   ei  = (const int*)d_in[1];
    const float* g1w = (const float*)d_in[2];
    const float* g1b = (const float*)d_in[3];
    const float* e1w = (const float*)d_in[4];
    const float* e1b = (const float*)d_in[5];
    const float* e2w = (const float*)d_in[6];
    const float* e2b = (const float*)d_in[7];
    const float* g2w = (const float*)d_in[8];
    const float* g2b = (const float*)d_in[9];
    float* out = (float*)d_out;

    k_prep<<<(EE + 255) / 256, 256>>>(ei);
    k_scan1<<<SNB, SB>>>();
    k_scan3<<<SNB, SB>>>();
    k_scatter<<<(EE + 255) / 256, 256>>>(ei);

    int hpqsmem = (CIN * CH + 64 + 64 * 128 + 64 + 64 * 68 + 8 * 32) * (int)sizeof(float);
    cudaFuncSetAttribute(k_hpq, cudaFuncAttributeMaxDynamicSharedMemorySize, hpqsmem);
    k_hpq<<<(NN + 63) / 64, 256, hpqsmem>>>(x, g1w, g1b, e1w, e1b);

    int smem = EC_FLTS * (int)sizeof(float);
    cudaFuncSetAttribute(k_edgeconv, cudaFuncAttributeMaxDynamicSharedMemorySize, smem);
    k_edgeconv<<<592, 256, smem>>>(e2w, e2b);

    k_z<<<(NN * COUT + 255) / 256, 256>>>(g2w);
    k_out<<<(NN * 16 + 255) / 256, 256>>>(g2b, out);
}